// round 15
// baseline (speedup 1.0000x reference)
#include <cuda_runtime.h>
#include <cuda_fp16.h>

// Sinkhorn-Knopp, 5 iterations, linear-domain scaling vectors, persistent
// L2-resident formulation with an fp16 exp(A) cache.
//
//   a_i = 1 / sum_j exp(A_ij) * b_j   (b init 1)
//   b_j = 1 / sum_i exp(A_ij) * a_i   (uses fresh a)
//   out = exp(A_ij) * a_i * b_j
//
// 16 groups x 8 CTAs, 1 CTA/SM (136 KB SMEM) -> all 128 CTAs co-resident,
// so the intra-group spin barrier cannot deadlock. Each CTA owns a fixed
// 128-row slice per matrix. Iteration 0 reads A (the ONLY DRAM read of A),
// computes exp once, and writes an fp16 cache; iterations 1-4 and the final
// pass reload the cache (CTA-private -> L1/L2 hits, half the bytes of fp32).

#define BATCH 64
#define N 1024
#define GROUPS 16
#define CPG 8                       // CTAs per group
#define MPG 4                       // matrices per group
#define ROWS_PER_CTA 128            // N / CPG
#define CHUNK 32                    // rows staged in SMEM at a time
#define NCHUNKS (ROWS_PER_CTA / CHUNK)
#define THREADS 1024
#define ITERS 5
#define PHASES (MPG * ITERS)

// Scratch (allocation-free: __device__ globals)
__device__ __half g_e[(size_t)BATCH * N * N];   // 128 MB fp16 exp cache
__device__ float  g_part[GROUPS][2][CPG][N];    // ping-pong column partials
__device__ int    g_bar[GROUPS][PHASES];        // one-shot barrier slots

__global__ __launch_bounds__(THREADS, 1)
void sinkhorn_persistent(const float* __restrict__ A, float* __restrict__ out)
{
    __shared__ float bs[N];                  // current column scales b
    __shared__ float a_sm[ROWS_PER_CTA];     // row scales a for owned rows
    extern __shared__ float tile[];          // CHUNK * N floats = 128 KB

    const int tid = threadIdx.x;
    const int g   = blockIdx.x / CPG;
    const int c   = blockIdx.x % CPG;
    const int w   = tid >> 5;                // warp 0..31
    const int l   = tid & 31;

    for (int k = 0; k < MPG; k++) {
        const int m = g * MPG + k;
        const size_t base = (size_t)m * N * N + (size_t)c * ROWS_PER_CTA * N;
        const float* Am = A   + base;
        __half*      Em = g_e + base;

        bs[tid] = 1.0f;                      // ordered by iter-top syncthreads

        for (int it = 0; it < ITERS; it++) {
            float col_r = 0.0f;              // this thread owns column `tid`
            __syncthreads();                 // bs visible, tile free

            for (int ch = 0; ch < NCHUNKS; ch++) {
                // ---- Phase A: warp w owns row ch*32+w.
                //      a = 1 / sum_j e_ij * b_j ; stage e in SMEM tile. ----
                const int row = ch * CHUNK + w;
                float4*       t4 = reinterpret_cast<float4*>(tile + w * N);
                const float4* b4 = reinterpret_cast<const float4*>(bs);

                float acc = 0.0f;
                if (it == 0) {
                    const float4* A4 =
                        reinterpret_cast<const float4*>(Am + (size_t)row * N);
                    uint2* E2 =
                        reinterpret_cast<uint2*>(Em + (size_t)row * N);
                    #pragma unroll
                    for (int q = 0; q < 8; q++) {
                        int c4 = q * 32 + l;
                        float4 v = A4[c4];
                        float4 e;
                        e.x = __expf(v.x); e.y = __expf(v.y);
                        e.z = __expf(v.z); e.w = __expf(v.w);
                        t4[c4] = e;
                        __half2 h01 = __floats2half2_rn(e.x, e.y);
                        __half2 h23 = __floats2half2_rn(e.z, e.w);
                        uint2 h;
                        h.x = *reinterpret_cast<unsigned*>(&h01);
                        h.y = *reinterpret_cast<unsigned*>(&h23);
                        E2[c4] = h;
                        float4 bb = b4[c4];
                        acc += e.x * bb.x + e.y * bb.y
                             + e.z * bb.z + e.w * bb.w;
                    }
                } else {
                    const uint2* E2 =
                        reinterpret_cast<const uint2*>(Em + (size_t)row * N);
                    #pragma unroll
                    for (int q = 0; q < 8; q++) {
                        int c4 = q * 32 + l;
                        uint2 h = E2[c4];
                        float2 f01 = __half22float2(
                            *reinterpret_cast<__half2*>(&h.x));
                        float2 f23 = __half22float2(
                            *reinterpret_cast<__half2*>(&h.y));
                        float4 e = make_float4(f01.x, f01.y, f23.x, f23.y);
                        t4[c4] = e;
                        float4 bb = b4[c4];
                        acc += e.x * bb.x + e.y * bb.y
                             + e.z * bb.z + e.w * bb.w;
                    }
                }
                #pragma unroll
                for (int o = 16; o; o >>= 1)
                    acc += __shfl_xor_sync(0xffffffffu, acc, o);
                if (l == 0) a_sm[row] = 1.0f / acc;
                __syncthreads();

                // ---- Phase B: column partials over this chunk ----
                float s = 0.0f;
                #pragma unroll
                for (int i = 0; i < CHUNK; i++)
                    s += tile[i * N + tid] * a_sm[ch * CHUNK + i];
                col_r += s;
                __syncthreads();             // tile reused by next chunk
            }

            // ---- Publish partials, group barrier, update b ----
            const int p   = k * ITERS + it;
            const int buf = p & 1;
            g_part[g][buf][c][tid] = col_r;
            __threadfence();                 // release partials device-wide
            __syncthreads();
            if (tid == 0) {
                atomicAdd(&g_bar[g][p], 1);
                while (atomicAdd(&g_bar[g][p], 0) < CPG) {}
            }
            __syncthreads();

            float s2 = 0.0f;
            #pragma unroll
            for (int cc = 0; cc < CPG; cc++)
                s2 += __ldcg(&g_part[g][buf][cc][tid]);
            bs[tid] = 1.0f / s2;
        }
        __syncthreads();                     // bs, a_sm final & visible

        // ---- Final pass: out = e * a_i * b_j from the fp16 cache ----
        const uint2* E2 = reinterpret_cast<const uint2*>(Em);
        float4* O4 = reinterpret_cast<float4*>(out + base);
        const float4* b4 = reinterpret_cast<const float4*>(bs);
        #pragma unroll 4
        for (int idx = tid; idx < ROWS_PER_CTA * (N / 4); idx += THREADS) {
            int row = idx >> 8;
            int c4  = idx & 255;
            float  a  = a_sm[row];
            uint2  h  = E2[idx];
            float2 f01 = __half22float2(*reinterpret_cast<__half2*>(&h.x));
            float2 f23 = __half22float2(*reinterpret_cast<__half2*>(&h.y));
            float4 bb = b4[c4];
            float4 o;
            o.x = f01.x * a * bb.x;
            o.y = f01.y * a * bb.y;
            o.z = f23.x * a * bb.z;
            o.w = f23.y * a * bb.w;
            O4[idx] = o;
        }
        __syncthreads();                     // a_sm/bs reads done before reuse
    }
}

extern "C" void kernel_launch(void* const* d_in, const int* in_sizes, int n_in,
                              void* d_out, int out_size)
{
    (void)in_sizes; (void)n_in; (void)out_size;
    const float* A   = (const float*)d_in[0];
    float*       out = (float*)d_out;

    cudaFuncSetAttribute(sinkhorn_persistent,
                         cudaFuncAttributeMaxDynamicSharedMemorySize,
                         CHUNK * N * (int)sizeof(float));

    // Barrier slots must be zero on every graph replay.
    void* bar_ptr = nullptr;
    cudaGetSymbolAddress(&bar_ptr, g_bar);
    cudaMemsetAsync(bar_ptr, 0, sizeof(int) * GROUPS * PHASES);

    sinkhorn_persistent<<<GROUPS * CPG, THREADS,
                          CHUNK * N * sizeof(float)>>>(A, out);
}

// round 16
// speedup vs baseline: 1.2644x; 1.2644x over previous
#include <cuda_runtime.h>
#include <cuda_fp16.h>

// Sinkhorn-Knopp, 5 iterations, linear-domain scaling vectors, persistent
// L2-resident formulation with an fp16 exp(A) cache and NO smem transpose:
// the column pass re-streams the CTA-private cache slice row-major with
// per-thread register accumulators (coalesced, barrier-light).
//
//   a_i = 1 / sum_j exp(A_ij) * b_j   (b init 1)
//   b_j = 1 / sum_i exp(A_ij) * a_i   (uses fresh a)
//   out = exp(A_ij) * a_i * b_j
//
// 16 groups x 8 CTAs (128 CTAs, 1 CTA/SM by register pressure) -> all
// co-resident, so the intra-group spin barrier cannot deadlock. Each CTA
// owns a fixed 128-row slice per matrix; all slice re-reads hit L2
// (live set = 16 matrices x 2MB fp16 = 32 MB).

#define BATCH 64
#define N 1024
#define GROUPS 16
#define CPG 8                       // CTAs per group
#define MPG 4                       // matrices per group
#define ROWS_PER_CTA 128
#define THREADS 1024
#define ITERS 5
#define PHASES (MPG * ITERS)

// Scratch (allocation-free: __device__ globals)
__device__ __half g_e[(size_t)BATCH * N * N];   // 128 MB fp16 exp cache
__device__ float  g_part[GROUPS][2][CPG][N];    // ping-pong column partials
__device__ int    g_bar[GROUPS][PHASES];        // one-shot barrier slots

__global__ __launch_bounds__(THREADS, 1)
void sinkhorn_persistent(const float* __restrict__ A, float* __restrict__ out)
{
    __shared__ float bs[N];                  // current column scales b
    __shared__ float a_sm[ROWS_PER_CTA];     // row scales for owned rows
    __shared__ float part4[4 * N];           // col-pass partial combine

    const int tid = threadIdx.x;
    const int g   = blockIdx.x / CPG;
    const int c   = blockIdx.x % CPG;
    const int w   = tid >> 5;                // warp 0..31
    const int l   = tid & 31;

    for (int k = 0; k < MPG; k++) {
        const int m = g * MPG + k;
        const size_t base = (size_t)m * N * N + (size_t)c * ROWS_PER_CTA * N;
        const float* Am = A   + base;
        __half*      Em = g_e + base;

        bs[tid] = 1.0f;                      // ordered by iter-top sync

        for (int it = 0; it < ITERS; it++) {
            __syncthreads();                 // bs visible

            // ---- ROW PASS: warp w owns rows 4w..4w+3.
            //      a_i = 1 / sum_j e_ij * b_j  (iter 0: compute+cache exp)
            const float4* b4 = reinterpret_cast<const float4*>(bs);
            #pragma unroll
            for (int r = 0; r < 4; r++) {
                const int row = w * 4 + r;
                float acc = 0.0f;
                if (it == 0) {
                    const float4* A4 =
                        reinterpret_cast<const float4*>(Am + (size_t)row * N);
                    uint2* E2 =
                        reinterpret_cast<uint2*>(Em + (size_t)row * N);
                    #pragma unroll
                    for (int q = 0; q < 8; q++) {
                        int c4 = q * 32 + l;
                        float4 v = A4[c4];
                        float4 e;
                        e.x = __expf(v.x); e.y = __expf(v.y);
                        e.z = __expf(v.z); e.w = __expf(v.w);
                        __half2 h01 = __floats2half2_rn(e.x, e.y);
                        __half2 h23 = __floats2half2_rn(e.z, e.w);
                        uint2 h;
                        h.x = *reinterpret_cast<unsigned*>(&h01);
                        h.y = *reinterpret_cast<unsigned*>(&h23);
                        E2[c4] = h;
                        float4 bb = b4[c4];
                        acc += e.x * bb.x + e.y * bb.y
                             + e.z * bb.z + e.w * bb.w;
                    }
                } else {
                    const uint2* E2 =
                        reinterpret_cast<const uint2*>(Em + (size_t)row * N);
                    #pragma unroll
                    for (int q = 0; q < 8; q++) {
                        int c4 = q * 32 + l;
                        uint2 h = E2[c4];
                        float2 f01 = __half22float2(
                            *reinterpret_cast<__half2*>(&h.x));
                        float2 f23 = __half22float2(
                            *reinterpret_cast<__half2*>(&h.y));
                        float4 bb = b4[c4];
                        acc += f01.x * bb.x + f01.y * bb.y
                             + f23.x * bb.z + f23.y * bb.w;
                    }
                }
                #pragma unroll
                for (int o = 16; o; o >>= 1)
                    acc += __shfl_xor_sync(0xffffffffu, acc, o);
                if (l == 0) a_sm[row] = 1.0f / acc;
            }
            __syncthreads();                 // a_sm ready

            // ---- COL PASS: thread owns 4 columns (one uint2), streams 32
            //      rows of the slice; 4 row-quarters combined via SMEM. ----
            const int colgrp = tid & 255;    // uint2 index within a row
            const int rh     = tid >> 8;     // row-quarter 0..3
            const uint2* E2s = reinterpret_cast<const uint2*>(Em);
            float4 cacc = make_float4(0.f, 0.f, 0.f, 0.f);
            #pragma unroll 8
            for (int i = 0; i < 32; i++) {
                int row = rh * 32 + i;
                uint2 h = E2s[row * (N / 4) + colgrp];
                float2 f01 = __half22float2(*reinterpret_cast<__half2*>(&h.x));
                float2 f23 = __half22float2(*reinterpret_cast<__half2*>(&h.y));
                float a = a_sm[row];
                cacc.x += f01.x * a;
                cacc.y += f01.y * a;
                cacc.z += f23.x * a;
                cacc.w += f23.y * a;
            }
            reinterpret_cast<float4*>(part4 + rh * N)[colgrp] = cacc;
            __syncthreads();
            float col_r = part4[tid] + part4[N + tid]
                        + part4[2 * N + tid] + part4[3 * N + tid];

            // ---- Publish partials, group barrier, update b ----
            const int p   = k * ITERS + it;
            const int buf = p & 1;
            g_part[g][buf][c][tid] = col_r;
            __threadfence();                 // release partials device-wide
            __syncthreads();
            if (tid == 0) {
                atomicAdd(&g_bar[g][p], 1);
                while (atomicAdd(&g_bar[g][p], 0) < CPG) {}
            }
            __syncthreads();

            float s2 = 0.0f;
            #pragma unroll
            for (int cc = 0; cc < CPG; cc++)
                s2 += __ldcg(&g_part[g][buf][cc][tid]);
            bs[tid] = 1.0f / s2;
        }
        __syncthreads();                     // bs, a_sm final & visible

        // ---- Final pass: out = e * a_i * b_j from the fp16 cache ----
        const uint2* E2 = reinterpret_cast<const uint2*>(Em);
        float4* O4 = reinterpret_cast<float4*>(out + base);
        const float4* b4 = reinterpret_cast<const float4*>(bs);
        #pragma unroll 4
        for (int idx = tid; idx < ROWS_PER_CTA * (N / 4); idx += THREADS) {
            int row = idx >> 8;
            int c4  = idx & 255;
            float  a  = a_sm[row];
            uint2  h  = E2[idx];
            float2 f01 = __half22float2(*reinterpret_cast<__half2*>(&h.x));
            float2 f23 = __half22float2(*reinterpret_cast<__half2*>(&h.y));
            float4 bb = b4[c4];
            float4 o;
            o.x = f01.x * a * bb.x;
            o.y = f01.y * a * bb.y;
            o.z = f23.x * a * bb.z;
            o.w = f23.y * a * bb.w;
            O4[idx] = o;
        }
        __syncthreads();                     // a_sm/bs reads done before reuse
    }
}

extern "C" void kernel_launch(void* const* d_in, const int* in_sizes, int n_in,
                              void* d_out, int out_size)
{
    (void)in_sizes; (void)n_in; (void)out_size;
    const float* A   = (const float*)d_in[0];
    float*       out = (float*)d_out;

    // Barrier slots must be zero on every graph replay.
    void* bar_ptr = nullptr;
    cudaGetSymbolAddress(&bar_ptr, g_bar);
    cudaMemsetAsync(bar_ptr, 0, sizeof(int) * GROUPS * PHASES);

    sinkhorn_persistent<<<GROUPS * CPG, THREADS>>>(A, out);
}